// round 16
// baseline (speedup 1.0000x reference)
#include <cuda_runtime.h>
#include <cuda_bf16.h>
#include <cstdint>

#define S_LEN 2048
#define HIDDEN 3584
#define N_HEADS 28
#define N_KV 4
#define HEAD_DIM 128
#define GROUPS 7
#define QKV_N (N_HEADS * HEAD_DIM + 2 * N_KV * HEAD_DIM)   // 4608
#define ATTN_SCALE 0.08838834764831845f

// ===================== device scratch ========================================
__device__ float g_q[N_HEADS * S_LEN * HEAD_DIM];
__device__ float g_k[N_KV * S_LEN * HEAD_DIM];

__device__ __nv_bfloat16 g_x_hi[S_LEN * HIDDEN];
__device__ __nv_bfloat16 g_x_lo[S_LEN * HIDDEN];
__device__ __nv_bfloat16 g_w_hi[QKV_N * HIDDEN];
__device__ __nv_bfloat16 g_w_lo[QKV_N * HIDDEN];
__device__ __nv_bfloat16 g_wo_hi[HIDDEN * HIDDEN];
__device__ __nv_bfloat16 g_wo_lo[HIDDEN * HIDDEN];
__device__ __nv_bfloat16 g_at_hi[S_LEN * HIDDEN];
__device__ __nv_bfloat16 g_at_lo[S_LEN * HIDDEN];

__device__ __nv_bfloat16 g_q_hi[N_HEADS * S_LEN * HEAD_DIM];
__device__ __nv_bfloat16 g_q_lo[N_HEADS * S_LEN * HEAD_DIM];
__device__ __nv_bfloat16 g_k_hi[N_KV * S_LEN * HEAD_DIM];
__device__ __nv_bfloat16 g_k_lo[N_KV * S_LEN * HEAD_DIM];
__device__ __nv_bfloat16 g_vT_hi[N_KV * HEAD_DIM * S_LEN];   // [kv][d][s]
__device__ __nv_bfloat16 g_vT_lo[N_KV * HEAD_DIM * S_LEN];

// ===================== low-level helpers =====================================
__device__ __forceinline__ uint32_t smem_u32(const void* p) {
    uint32_t a;
    asm("{ .reg .u64 t; cvta.to.shared.u64 t, %1; cvt.u32.u64 %0, t; }"
        : "=r"(a) : "l"(p));
    return a;
}
__device__ __forceinline__ void cp16(uint32_t s, const void* g) {
    asm volatile("cp.async.cg.shared.global [%0], [%1], 16;" :: "r"(s), "l"(g));
}
#define CP_COMMIT() asm volatile("cp.async.commit_group;" ::: "memory")
#define CP_WAIT2()  asm volatile("cp.async.wait_group 2;" ::: "memory")
#define CP_WAIT1()  asm volatile("cp.async.wait_group 1;" ::: "memory")
#define CP_WAIT0()  asm volatile("cp.async.wait_group 0;" ::: "memory")

__device__ __forceinline__ void ldm4(uint32_t& r0, uint32_t& r1, uint32_t& r2,
                                     uint32_t& r3, uint32_t a) {
    asm volatile("ldmatrix.sync.aligned.m8n8.x4.shared.b16 {%0,%1,%2,%3}, [%4];"
        : "=r"(r0), "=r"(r1), "=r"(r2), "=r"(r3) : "r"(a));
}
__device__ __forceinline__ void mma16816(float* c, const uint32_t* a,
                                         const uint32_t* b) {
    asm volatile(
        "mma.sync.aligned.m16n8k16.row.col.f32.bf16.bf16.f32 "
        "{%0,%1,%2,%3}, {%4,%5,%6,%7}, {%8,%9}, {%0,%1,%2,%3};"
        : "+f"(c[0]), "+f"(c[1]), "+f"(c[2]), "+f"(c[3])
        : "r"(a[0]), "r"(a[1]), "r"(a[2]), "r"(a[3]), "r"(b[0]), "r"(b[1]));
}

__device__ __forceinline__ uint32_t pack_hilo(float x, float y, uint32_t& lo) {
    __nv_bfloat16 hx = __float2bfloat16(x);
    __nv_bfloat16 hy = __float2bfloat16(y);
    __nv_bfloat16 lx = __float2bfloat16(x - __bfloat162float(hx));
    __nv_bfloat16 ly = __float2bfloat16(y - __bfloat162float(hy));
    lo = (uint32_t)__bfloat16_as_ushort(lx) | ((uint32_t)__bfloat16_as_ushort(ly) << 16);
    return (uint32_t)__bfloat16_as_ushort(hx) | ((uint32_t)__bfloat16_as_ushort(hy) << 16);
}

// ===================== mma.sync GEMM core (128x128, 2 CTA/SM) ================
#define ROW_STRIDE_B 80                 // 32 bf16 (64B) + 16B pad
#define MAT_BYTES (128 * ROW_STRIDE_B)  // 10240
#define STAGE_BYTES (4 * MAT_BYTES)     // 40960
#define GEMM_SMEM (2 * STAGE_BYTES)     // 81920  -> 2 CTAs/SM

// ld = row stride of A/B in elements; kb = column offset of this chunk.
__device__ __forceinline__ void load_stage(
    const __nv_bfloat16* a_hi, const __nv_bfloat16* a_lo,
    const __nv_bfloat16* b_hi, const __nv_bfloat16* b_lo,
    int ld, int kb, uint32_t sbase, int tid)
{
    const __nv_bfloat16* ptrs[4] = {a_hi, a_lo, b_hi, b_lo};
    #pragma unroll
    for (int i = 0; i < 8; ++i) {
        int idx = tid + i * 256;        // 0..2047
        int mat = idx >> 9;             // 0..3
        int rem = idx & 511;
        int row = rem >> 2;
        int cp  = rem & 3;
        const __nv_bfloat16* src = ptrs[mat] + (size_t)row * ld + kb + cp * 8;
        cp16(sbase + mat * MAT_BYTES + row * ROW_STRIDE_B + cp * 16, src);
    }
}

__device__ __forceinline__ void compute_stage(
    uint32_t sbase, int warp_m, int warp_n, int lane, float acc[2][8][4])
{
    const uint32_t ahB = sbase;
    const uint32_t alB = sbase + MAT_BYTES;
    const uint32_t bhB = sbase + 2 * MAT_BYTES;
    const uint32_t blB = sbase + 3 * MAT_BYTES;

    const int lrow = lane & 15;
    const int lk   = (lane >> 4) * 8;
    const int g    = lane >> 3;
    const int nadd = ((g >> 1) << 3) + (lane & 7);
    const int kadd = (g & 1) * 8;

    #pragma unroll
    for (int ks = 0; ks < 2; ++ks) {
        uint32_t ah[2][4], al[2][4];
        #pragma unroll
        for (int mf = 0; mf < 2; ++mf) {
            uint32_t off = (uint32_t)(warp_m * 32 + mf * 16 + lrow) * ROW_STRIDE_B
                         + (ks * 16 + lk) * 2;
            ldm4(ah[mf][0], ah[mf][1], ah[mf][2], ah[mf][3], ahB + off);
            ldm4(al[mf][0], al[mf][1], al[mf][2], al[mf][3], alB + off);
        }
        #pragma unroll
        for (int nf2 = 0; nf2 < 4; ++nf2) {
            uint32_t off = (uint32_t)(warp_n * 64 + nf2 * 16 + nadd) * ROW_STRIDE_B
                         + (ks * 16 + kadd) * 2;
            uint32_t bh[4], bl[4];
            ldm4(bh[0], bh[1], bh[2], bh[3], bhB + off);
            ldm4(bl[0], bl[1], bl[2], bl[3], blB + off);
            #pragma unroll
            for (int mf = 0; mf < 2; ++mf) {
                mma16816(acc[mf][nf2*2],   ah[mf], bh);
                mma16816(acc[mf][nf2*2],   ah[mf], bl);
                mma16816(acc[mf][nf2*2],   al[mf], bh);
                mma16816(acc[mf][nf2*2+1], ah[mf], bh + 2);
                mma16816(acc[mf][nf2*2+1], ah[mf], bl + 2);
                mma16816(acc[mf][nf2*2+1], al[mf], bh + 2);
            }
        }
    }
}

// klen = number of K columns to process (multiple of 32); ld = row stride.
__device__ __forceinline__ void gemm_main(
    const __nv_bfloat16* ahi, const __nv_bfloat16* alo,
    const __nv_bfloat16* bhi, const __nv_bfloat16* blo,
    int ld, int klen, char* sm, float acc[2][8][4])
{
    const int tid = threadIdx.x;
    const int wid = tid >> 5;
    const int lane = tid & 31;
    const int warp_m = wid & 3;
    const int warp_n = wid >> 2;
    const uint32_t smb = smem_u32(sm);

    #pragma unroll
    for (int mf = 0; mf < 2; ++mf)
        #pragma unroll
        for (int nf = 0; nf < 8; ++nf)
            #pragma unroll
            for (int r = 0; r < 4; ++r) acc[mf][nf][r] = 0.f;

    const int nIters = klen / 32;
    load_stage(ahi, alo, bhi, blo, ld, 0, smb, tid);
    CP_COMMIT();
    load_stage(ahi, alo, bhi, blo, ld, 32, smb + STAGE_BYTES, tid);
    CP_COMMIT();

    for (int c = 0; c < nIters; ++c) {
        CP_WAIT1();
        __syncthreads();
        compute_stage(smb + (c & 1) * STAGE_BYTES, warp_m, warp_n, lane, acc);
        __syncthreads();
        if (c + 2 < nIters)
            load_stage(ahi, alo, bhi, blo, ld, (c + 2) * 32,
                       smb + (c & 1) * STAGE_BYTES, tid);
        CP_COMMIT();
    }
    CP_WAIT0();
}

// ===================== QKV projection (V tiles scheduled first) ==============
__global__ __launch_bounds__(256, 2)
void qkv_mma_kernel(const float* __restrict__ bq, const float* __restrict__ bk,
                    const float* __restrict__ bv)
{
    extern __shared__ __align__(128) char sm[];
    const int m0 = blockIdx.x * 128;
    const int n0 = (35 - (int)blockIdx.y) * 128;   // reversed: V tiles first

    float acc[2][8][4];
    gemm_main(g_x_hi + (size_t)m0 * HIDDEN,
              g_x_lo + (size_t)m0 * HIDDEN,
              g_w_hi + (size_t)n0 * HIDDEN,
              g_w_lo + (size_t)n0 * HIDDEN,
              HIDDEN, HIDDEN, sm, acc);

    const int tid = threadIdx.x;
    const int wid = tid >> 5;
    const int lane = tid & 31;
    const int warp_m = wid & 3;
    const int warp_n = wid >> 2;

    if (n0 < (N_HEADS + N_KV) * HEAD_DIM) {
        float* dst;
        const float* bias;
        if (n0 < N_HEADS * HEAD_DIM) {
            dst = g_q + (size_t)(n0 >> 7) * S_LEN * HEAD_DIM; bias = bq + n0;
        } else {
            int o = n0 - N_HEADS * HEAD_DIM;
            dst = g_k + (size_t)(o >> 7) * S_LEN * HEAD_DIM; bias = bk + o;
        }
        #pragma unroll
        for (int mf = 0; mf < 2; ++mf) {
            int row = m0 + warp_m * 32 + mf * 16 + (lane >> 2);
            #pragma unroll
            for (int nf = 0; nf < 8; ++nf) {
                int col = warp_n * 64 + nf * 8 + (lane & 3) * 2;
                float b0 = bias[col], b1 = bias[col + 1];
                dst[(size_t)row * HEAD_DIM + col]           = acc[mf][nf][0] + b0;
                dst[(size_t)row * HEAD_DIM + col + 1]       = acc[mf][nf][1] + b1;
                dst[(size_t)(row + 8) * HEAD_DIM + col]     = acc[mf][nf][2] + b0;
                dst[(size_t)(row + 8) * HEAD_DIM + col + 1] = acc[mf][nf][3] + b1;
            }
        }
    } else {
        int o = n0 - (N_HEADS + N_KV) * HEAD_DIM;
        int head = o >> 7;
        const float* bias = bv + o;

        __syncthreads();
        float* T = reinterpret_cast<float*>(sm);   // [128][133]
        #pragma unroll
        for (int mf = 0; mf < 2; ++mf) {
            int r0 = warp_m * 32 + mf * 16 + (lane >> 2);
            #pragma unroll
            for (int nf = 0; nf < 8; ++nf) {
                int col = warp_n * 64 + nf * 8 + (lane & 3) * 2;
                float b0 = bias[col], b1 = bias[col + 1];
                T[r0 * 133 + col]           = acc[mf][nf][0] + b0;
                T[r0 * 133 + col + 1]       = acc[mf][nf][1] + b1;
                T[(r0 + 8) * 133 + col]     = acc[mf][nf][2] + b0;
                T[(r0 + 8) * 133 + col + 1] = acc[mf][nf][3] + b1;
            }
        }
        __syncthreads();

        int d  = tid >> 1;
        int sc = (tid & 1) * 64;
        size_t base = (size_t)head * HEAD_DIM * S_LEN + (size_t)d * S_LEN + m0 + sc;
        __nv_bfloat16* hi = g_vT_hi + base;
        __nv_bfloat16* lo = g_vT_lo + base;
        #pragma unroll
        for (int j = 0; j < 64; j += 2) {
            float a = T[(sc + j) * 133 + d];
            float b = T[(sc + j + 1) * 133 + d];
            uint32_t L;
            uint32_t H = pack_hilo(a, b, L);
            *reinterpret_cast<uint32_t*>(hi + j) = H;
            *reinterpret_cast<uint32_t*>(lo + j) = L;
        }
    }
}

// ===================== output projection (split-K=2, atomic accumulate) ======
__global__ __launch_bounds__(256, 2)
void out_mma_kernel(float* __restrict__ out)
{
    extern __shared__ __align__(128) char sm[];
    const int m0 = blockIdx.x * 128;
    const int n0 = blockIdx.y * 128;
    const int k0 = blockIdx.z * (HIDDEN / 2);      // 0 or 1792

    float acc[2][8][4];
    gemm_main(g_at_hi + (size_t)m0 * HIDDEN + k0,
              g_at_lo + (size_t)m0 * HIDDEN + k0,
              g_wo_hi + (size_t)n0 * HIDDEN + k0,
              g_wo_lo + (size_t)n0 * HIDDEN + k0,
              HIDDEN, HIDDEN / 2, sm, acc);

    const int tid = threadIdx.x;
    const int wid = tid >> 5;
    const int lane = tid & 31;
    const int warp_m = wid & 3;
    const int warp_n = wid >> 2;

    #pragma unroll
    for (int mf = 0; mf < 2; ++mf) {
        int row = m0 + warp_m * 32 + mf * 16 + (lane >> 2);
        #pragma unroll
        for (int nf = 0; nf < 8; ++nf) {
            int col = n0 + warp_n * 64 + nf * 8 + (lane & 3) * 2;
            atomicAdd(&out[(size_t)row * HIDDEN + col],           acc[mf][nf][0]);
            atomicAdd(&out[(size_t)row * HIDDEN + col + 1],       acc[mf][nf][1]);
            atomicAdd(&out[(size_t)(row + 8) * HIDDEN + col],     acc[mf][nf][2]);
            atomicAdd(&out[(size_t)(row + 8) * HIDDEN + col + 1], acc[mf][nf][3]);
        }
    }
}

// ===================== merged fp32 -> bf16 hi/lo split (all tensors) =========
#define CVT_X  (S_LEN * HIDDEN / 4)
#define CVT_WQ (N_HEADS * HEAD_DIM * HIDDEN / 4)
#define CVT_WK (N_KV * HEAD_DIM * HIDDEN / 4)
#define CVT_WO (HIDDEN * HIDDEN / 4)
#define CVT_TOTAL (CVT_X + CVT_WQ + 2 * CVT_WK + CVT_WO)

__global__ void cvt_all_kernel(const float* __restrict__ X,
                               const float* __restrict__ Wq,
                               const float* __restrict__ Wk,
                               const float* __restrict__ Wv,
                               const float* __restrict__ Wo)
{
    int i = blockIdx.x * blockDim.x + threadIdx.x;
    if (i >= CVT_TOTAL) return;

    const float* src;
    __nv_bfloat16 *hi, *lo;
    int j;
    if (i < CVT_X) {
        src = X; j = i; hi = g_x_hi; lo = g_x_lo;
    } else if (i < CVT_X + CVT_WQ) {
        src = Wq; j = i - CVT_X; hi = g_w_hi; lo = g_w_lo;
    } else if (i < CVT_X + CVT_WQ + CVT_WK) {
        src = Wk; j = i - CVT_X - CVT_WQ;
        hi = g_w_hi + (size_t)N_HEADS * HEAD_DIM * HIDDEN;
        lo = g_w_lo + (size_t)N_HEADS * HEAD_DIM * HIDDEN;
    } else if (i < CVT_X + CVT_WQ + 2 * CVT_WK) {
        src = Wv; j = i - CVT_X - CVT_WQ - CVT_WK;
        hi = g_w_hi + (size_t)(N_HEADS + N_KV) * HEAD_DIM * HIDDEN;
        lo = g_w_lo + (size_t)(N_HEADS + N_KV) * HEAD_DIM * HIDDEN;
    } else {
        src = Wo; j = i - CVT_X - CVT_WQ - 2 * CVT_WK;
        hi = g_wo_hi; lo = g_wo_lo;
    }

    float4 v = reinterpret_cast<const float4*>(src)[j];
    __nv_bfloat16 h0 = __float2bfloat16(v.x);
    __nv_bfloat16 h1 = __float2bfloat16(v.y);
    __nv_bfloat16 h2 = __float2bfloat16(v.z);
    __nv_bfloat16 h3 = __float2bfloat16(v.w);
    __nv_bfloat16 l0 = __float2bfloat16(v.x - __bfloat162float(h0));
    __nv_bfloat16 l1 = __float2bfloat16(v.y - __bfloat162float(h1));
    __nv_bfloat16 l2 = __float2bfloat16(v.z - __bfloat162float(h2));
    __nv_bfloat16 l3 = __float2bfloat16(v.w - __bfloat162float(h3));
    ushort4 hv, lv;
    hv.x = __bfloat16_as_ushort(h0); hv.y = __bfloat16_as_ushort(h1);
    hv.z = __bfloat16_as_ushort(h2); hv.w = __bfloat16_as_ushort(h3);
    lv.x = __bfloat16_as_ushort(l0); lv.y = __bfloat16_as_ushort(l1);
    lv.z = __bfloat16_as_ushort(l2); lv.w = __bfloat16_as_ushort(l3);
    reinterpret_cast<ushort4*>(hi)[j] = hv;
    reinterpret_cast<ushort4*>(lo)[j] = lv;
}

// ===================== RoPE + convert (vectorized x4) ========================
__global__ void rope_cvt_kernel(const float* __restrict__ cos_t,
                                const float* __restrict__ sin_t)
{
    int idx = blockIdx.x * blockDim.x + threadIdx.x;   // (N_HEADS+N_KV)*S*16
    if (idx >= (N_HEADS + N_KV) * S_LEN * 16) return;
    int d0 = (idx & 15) * 4;
    int s  = (idx >> 4) & (S_LEN - 1);
    int head = idx >> 15;

    const float* p;
    __nv_bfloat16 *hi, *lo;
    size_t base;
    if (head < N_HEADS) {
        base = (size_t)head * S_LEN * HEAD_DIM;
        p = g_q + base; hi = g_q_hi + base; lo = g_q_lo + base;
    } else {
        base = (size_t)(head - N_HEADS) * S_LEN * HEAD_DIM;
        p = g_k + base; hi = g_k_hi + base; lo = g_k_lo + base;
    }
    size_t o1 = (size_t)s * HEAD_DIM + d0;
    size_t o2 = o1 + 64;
    float4 c  = *reinterpret_cast<const float4*>(cos_t + s * HEAD_DIM + d0);
    float4 sn = *reinterpret_cast<const float4*>(sin_t + s * HEAD_DIM + d0);
    float4 x1 = *reinterpret_cast<const float4*>(p + o1);
    float4 x2 = *reinterpret_cast<const float4*>(p + o2);

    float y1[4], y2[4];
    y1[0] = x1.x * c.x - x2.x * sn.x;  y2[0] = x2.x * c.x + x1.x * sn.x;
    y1[1] = x1.y * c.y - x2.y * sn.y;  y2[1] = x2.y * c.y + x1.y * sn.y;
    y1[2] = x1.z * c.z - x2.z * sn.z;  y2[2] = x2.z * c.z + x1.z * sn.z;
    y1[3] = x1.w * c.w - x2.w * sn.w;  y2[3] = x2.w * c.w + x1.w * sn.w;

    uint2 H, L;
    uint32_t l0, l1;
    H.x = pack_hilo(y1[0], y1[1], l0);
    H.y = pack_hilo(y1[2], y1[3], l1);
    L.x = l0; L.y = l1;
    *reinterpret_cast<uint2*>(hi + o1) = H;
    *reinterpret_cast<uint2*>(lo + o1) = L;
    H.x = pack_hilo(y2[0], y2[1], l0);
    H.y = pack_hilo(y2[2], y2[3], l1);
    L.x = l0; L.y = l1;
    *reinterpret_cast<uint2*>(hi + o2) = H;
    *reinterpret_cast<uint2*>(lo + o2) = L;
}

// ===================== flash attention (software-pipelined S) =================
#define FL_QH 0u
#define FL_QL 34816u
#define FL_ST0 69632u
#define FL_STAGE 71680u
#define FL_KH 0u
#define FL_KL 17408u
#define FL_VH 34816u
#define FL_VL 53248u
#define FLASH_SMEM 212992

__device__ __forceinline__ void flash_load_k(
    uint32_t sbase, const __nv_bfloat16* kh_g, const __nv_bfloat16* kl_g,
    int key0, int tid)
{
    #pragma unroll
    for (int i = 0; i < 4; ++i) {
        int idx = tid + i * 256;
        int row = idx >> 4, cp = idx & 15;
        cp16(sbase + FL_KH + row * 272 + cp * 16,
             kh_g + (size_t)(key0 + row) * HEAD_DIM + cp * 8);
        cp16(sbase + FL_KL + row * 272 + cp * 16,
             kl_g + (size_t)(key0 + row) * HEAD_DIM + cp * 8);
    }
}
__device__ __forceinline__ void flash_load_v(
    uint32_t sbase, const __nv_bfloat16* vh_g, const __nv_bfloat16* vl_g,
    int key0, int tid)
{
    #pragma unroll
    for (int i = 0; i < 4; ++i) {
        int idx = tid + i * 256;
        int vrow = idx >> 3, vcp = idx & 7;
        cp16(sbase + FL_VH + vrow * 144 + vcp * 16,
             vh_g + (size_t)vrow * S_LEN + key0 + vcp * 8);
        cp16(sbase + FL_VL + vrow * 144 + vcp * 16,
             vl_g + (size_t)vrow * S_LEN + key0 + vcp * 8);
    }
}

__device__ __forceinline__ void flash_qk(
    float s[8][4], uint32_t smb, uint32_t stg,
    int wid, int lrow, int lk, int nadd, int kadd)
{
    #pragma unroll
    for (int nf = 0; nf < 8; ++nf)
        #pragma unroll
        for (int r = 0; r < 4; ++r) s[nf][r] = 0.f;
    #pragma unroll
    for (int ks = 0; ks < 8; ++ks) {
        uint32_t qh[4], ql[4];
        uint32_t qoff = (uint32_t)(wid * 16 + lrow) * 272 + (ks * 16 + lk) * 2;
        ldm4(qh[0], qh[1], qh[2], qh[3], smb + FL_QH + qoff);
        ldm4(ql[0], ql[1], ql[2], ql[3], smb + FL_QL + qoff);
        #pragma unroll
        for (int nf2 = 0; nf2 < 4; ++nf2) {
            uint32_t koff = (uint32_t)(nf2 * 16 + nadd) * 272 + (ks * 16 + kadd) * 2;
            uint32_t kh[4], kl[4];
            ldm4(kh[0], kh[1], kh[2], kh[3], stg + FL_KH + koff);
            ldm4(kl[0], kl[1], kl[2], kl[3], stg + FL_KL + koff);
            mma16816(s[nf2*2],   qh, kh);
            mma16816(s[nf2*2],   qh, kl);
            mma16816(s[nf2*2],   ql, kh);
            mma16816(s[nf2*2+1], qh, kh + 2);
            mma16816(s[nf2*2+1], qh, kl + 2);
            mma16816(s[nf2*2+1], ql, kh + 2);
        }
    }
}

__global__ __launch_bounds__(256, 1)
void flash_mma_kernel()
{
    extern __shared__ __align__(128) char sm[];
    const uint32_t smb = smem_u32(sm);
    const int qb  = 15 - (int)blockIdx.x;
    const int h   = blockIdx.y;
    const int kvh = h / GROUPS;
    const int tid = threadIdx.x;
    const int wid = tid >> 5;
    const int lane = tid & 31;
    const int lrow = lane & 15;
    const int lk   = (lane >> 4) * 8;
    const int g    = lane >> 3;
    const int nadd = ((g >> 1) << 3) + (lane & 7);
    const int kadd = (g & 1) * 8;

    const __nv_bfloat16* qh_g = g_q_hi + ((size_t)h * S_LEN + qb * 128) * HEAD_DIM;
    const __nv_bfloat16* ql_g = g_q_lo + ((size_t)h * S_LEN + qb * 128) * HEAD_DIM;
    const __nv_bfloat16* kh_g = g_k_hi + (size_t)kvh * S_LEN * HEAD_DIM;
    const __nv_bfloat16* kl_g = g_k_lo + (size_t)kvh * S_LEN * HEAD_DIM;
    const __nv_bfloat16* vh_g = g_vT_hi + (size_t)kvh * HEAD_DIM * S_LEN;
    const __nv_bfloat16* vl_g = g_vT_lo + (size_t)kvh * HEAD_DIM * S_LEN;

    const int nblk = 2 * qb + 2;

    #pragma unroll
    for (int i = 0; i < 8; ++i) {
        int idx = tid + i * 256;
        int row = idx >> 4, cp = idx & 15;
        cp16(smb + FL_QH + row * 272 + cp * 16, qh_g + (size_t)row * HEAD_DIM + cp * 8);
        cp16(smb + FL_QL + row * 272 + cp * 16, ql_g + (size_t)row * HEAD_DIM + cp * 8);
    }
    flash_load_k(smb + FL_ST0, kh_g, kl_g, 0, tid);
    flash_load_v(smb + FL_ST0, vh_g, vl_g, 0, tid);
    CP_COMMIT();
    flash_load_k(smb + FL_ST0 + FL_STAGE, kh_g, kl_g, 64, tid);
    CP_COMMIT();
    flash_load_v(smb + FL_ST0 + FL_STAGE, vh_g, vl_g, 64, tid);
    CP_COMMIT();

    CP_WAIT2();
    __syncthreads();
    float s_cur[8][4];
    flash_qk(s_cur, smb, smb + FL_ST0, wid, lrow, lk, nadd, kadd);

    float o[16][4];
    #pragma unroll
    for (int nf = 0; nf < 16; ++nf)
        #pragma unroll
        for (int r = 0; r < 4; ++r) o[nf][r] = 0.f;
    float m0 = -1e30f, m1 = -1e30f, l0 = 0.f, l1 = 0.f;
    const int qr0 = qb * 128 + wid * 16 + (lane >> 2);
    const int qr1 = qr0 + 8;

    for (int blk = 0; blk < nblk; ++blk) {
        const int key0 = blk * 64;
        const uint32_t stg_cur  = smb + FL_ST0 + (blk & 1) * FL_STAGE;
        const uint32_t stg_next = smb + FL_ST0 + ((blk + 1) & 1) * FL_STAGE;

        CP_WAIT1();
        __syncthreads();

        float s_next[8][4];
        if (blk + 1 < nblk)
            flash_qk(s_next, smb, stg_next, wid, lrow, lk, nadd, kadd);

        if (blk + 2 < nblk)
            flash_load_k(stg_cur, kh_g, kl_g, (blk + 2) * 64, tid);
        CP_COMMIT();

        if (blk >= 2 * qb) {
            #pragma unroll
            for (int nf = 0; nf < 8; ++nf) {
                int c0 = key0 + 8 * nf + 2 * (lane & 3);
                s_cur[nf][0] = (c0     > qr0) ? -1e30f : s_cur[nf][0] * ATTN_SCALE;
                s_cur[nf][1] = (c0 + 1 > qr0) ? -1e30f : s_cur[nf][1] * ATTN_SCALE;
                s_cur[nf][2] = (c0     > qr1) ? -1e30f : s_cur[nf][2] * ATTN_SCALE;
                s_cur[nf][3] = (c0 + 1 > qr1) ? -1e30f : s_cur[nf][3] * ATTN_SCALE;
            }
        } else {
            #pragma unroll
            for (int nf = 0; nf < 8; ++nf)
                #pragma unroll
                for (int r = 0; r < 4; ++r) s_cur[nf][r] *= ATTN_SCALE;
        }

        float mx0 = -1e30f, mx1 = -1e30f;
        #pragma unroll
        for (int nf = 0; nf < 8; ++nf) {
            mx0 = fmaxf(mx0, fmaxf(s_cur[nf][0], s_cur[nf][1]));
            mx1 = fmaxf(mx1, fmaxf(s_cur[nf][2], s_cur[nf][3]));
        }
        mx0 = fmaxf(mx0, __shfl_xor_sync(0xffffffffu, mx0, 1));
        mx0 = fmaxf(mx0, __shfl_xor_sync(0xffffffffu, mx0, 2));
        mx1 = fmaxf(mx1, __shfl_xor_sync(0xffffffffu, mx1, 1));
        mx1 = fmaxf(mx1, __shfl_xor_sync(0xffffffffu, mx1, 2));

        float mn0 = fmaxf(m0, mx0), mn1 = fmaxf(m1, mx1);
        float corr0 = __expf(m0 - mn0), corr1 = __expf(m1 - mn1);
        float sum0 = 0.f, sum1 = 0.f;
        #pragma unroll
        for (int nf = 0; nf < 8; ++nf) {
            s_cur[nf][0] = __expf(s_cur[nf][0] - mn0);
            s_cur[nf][1] = __expf(s_cur[nf][1] - mn0);
            s_cur[nf][2] = __expf(s_cur[nf][2] - mn1);
            s_cur[nf][3] = __expf(s_cur[nf][3] - mn1);
            sum0 += s_cur[nf][0] + s_cur[nf][1];
            sum1 += s_cur[nf][2] + s_cur[nf][3];
        }
        sum0 += __shfl_xor_sync(0xffffffffu, sum0, 1);
        sum0 += __shfl_xor_sync(0xffffffffu, sum0, 2);
        sum1 += __shfl_xor_sync(0xffffffffu, sum1, 1);
        sum1 += __shfl_xor_sync(0xffffffffu, sum1, 2);
        l0 = l0 * corr0 + sum0;  m0 = mn0;
        l1 = l1 * corr1 + sum1;  m1 = mn1;

        #pragma unroll
        for (int nf = 0; nf < 16; ++nf) {
            o[nf][0] *= corr0; o[nf][1] *= corr0;
            o[nf][2] *= corr1; o[nf][3] *= corr1;
        }

        #pragma unroll
        for (int ks = 0; ks < 4; ++ks) {
            int f0 = 2 * ks, f1 = f0 + 1;
            uint32_t ph[4], pl[4];
            ph[0] = pack_hilo(s_cur[f0][0], s_cur[f0][1], pl[0]);
            ph[1] = pack_hilo(s_cur[f0][2], s_cur[f0][3], pl[1]);
            ph[2] = pack_hilo(s_cur[f1][0], s_cur[f1][1], pl[2]);
            ph[3] = pack_hilo(s_cur[f1][2], s_cur[f1][3], pl[3]);
            #pragma unroll
            for (int nf2 = 0; nf2 < 8; ++nf2) {
                uint32_t voff = (uint32_t)(nf2 * 16 + nadd) * 144 + (ks * 16 + kadd) * 2;
                uint32_t vh[4], vl[4];
                ldm4(vh[0], vh[1], vh[2], vh[3], stg_cur + FL_VH + voff);
                ldm4(vl[0], vl[1], vl[2], vl[3], stg_cur + FL_VL + voff);
                mma16816(o[nf2*2],   ph, vh);
                mma16816(o[nf2*2],   pl, vh);
                mma16816(o[nf2*2],   ph, vl);
                mma16816(o[nf2*2+1], ph, vh + 2);
                mma16816(o[nf2*2+1], pl, vh + 2);
                mma16816(o[nf2*2+1], ph, vl + 2);
            }
        }

        __syncthreads();
        if (blk + 2 < nblk)
            flash_load_v(stg_cur, vh_g, vl_g, (blk + 2) * 64, tid);
        CP_COMMIT();

        #pragma unroll
        for (int nf = 0; nf < 8; ++nf)
            #pragma unroll
            for (int r = 0; r < 4; ++r) s_cur[nf][r] = s_next[nf][r];
    }

    float inv0 = 1.f / l0, inv1 = 1.f / l1;
    #pragma unroll
    for (int nf = 0; nf < 16; ++nf) {
        int dcol = 8 * nf + 2 * (lane & 3);
        size_t o0 = (size_t)qr0 * HIDDEN + h * HEAD_DIM + dcol;
        size_t o1 = (size_t)qr1 * HIDDEN + h * HEAD_DIM + dcol;
        uint32_t lo;
        uint32_t hi = pack_hilo(o[nf][0] * inv0, o[nf][1] * inv0, lo);
        *reinterpret_cast<uint32_t*>(g_at_hi + o0) = hi;
        *reinterpret_cast<uint32_t*>(g_at_lo + o0) = lo;
        hi = pack_hilo(o[nf][2] * inv1, o[nf][3] * inv1, lo);
        *reinterpret_cast<uint32_t*>(g_at_hi + o1) = hi;
        *reinterpret_cast<uint32_t*>(g_at_lo + o1) = lo;
    }
}

// ===================== launch ================================================
extern "C" void kernel_launch(void* const* d_in, const int* in_sizes, int n_in,
                              void* d_out, int out_size)
{
    const float* X    = (const float*)d_in[0];
    const float* cosT = (const float*)d_in[1];
    const float* sinT = (const float*)d_in[2];
    const float* Wq   = (const float*)d_in[3];
    const float* bq   = (const float*)d_in[4];
    const float* Wk   = (const float*)d_in[5];
    const float* bk   = (const float*)d_in[6];
    const float* Wv   = (const float*)d_in[7];
    const float* bv   = (const float*)d_in[8];
    const float* Wo   = (const float*)d_in[9];
    float* out = (float*)d_out;

    cudaFuncSetAttribute(qkv_mma_kernel,  cudaFuncAttributeMaxDynamicSharedMemorySize, GEMM_SMEM);
    cudaFuncSetAttribute(out_mma_kernel,  cudaFuncAttributeMaxDynamicSharedMemorySize, GEMM_SMEM);
    cudaFuncSetAttribute(flash_mma_kernel, cudaFuncAttributeMaxDynamicSharedMemorySize, FLASH_SMEM);

    // 0) zero output (split-K accumulates into it); async, graph-capturable
    cudaMemsetAsync(out, 0, (size_t)S_LEN * HIDDEN * sizeof(float));

    // 1) single merged conversion kernel
    cvt_all_kernel<<<(CVT_TOTAL + 255) / 256, 256>>>(X, Wq, Wk, Wv, Wo);

    // 2) QKV projection (V tiles first)
    qkv_mma_kernel<<<dim3(16, 36), 256, GEMM_SMEM>>>(bq, bk, bv);

    // 3) RoPE -> bf16 hi/lo (vectorized)
    {
        int n = (N_HEADS + N_KV) * S_LEN * 16;
        rope_cvt_kernel<<<(n + 255) / 256, 256>>>(cosT, sinT);
    }

    // 4) flash attention (software-pipelined)
    flash_mma_kernel<<<dim3(16, N_HEADS), 256, FLASH_SMEM>>>();

    // 5) output projection, split-K=2 (896 half-size CTAs -> better wave fill)
    out_mma_kernel<<<dim3(16, 28, 2), 256, GEMM_SMEM>>>(out);
}

// round 17
// speedup vs baseline: 1.0170x; 1.0170x over previous
#include <cuda_runtime.h>
#include <cuda_bf16.h>
#include <cstdint>

#define S_LEN 2048
#define HIDDEN 3584
#define N_HEADS 28
#define N_KV 4
#define HEAD_DIM 128
#define GROUPS 7
#define QKV_N (N_HEADS * HEAD_DIM + 2 * N_KV * HEAD_DIM)   // 4608
#define ATTN_SCALE 0.08838834764831845f

// ===================== device scratch ========================================
__device__ float g_q[N_HEADS * S_LEN * HEAD_DIM];
__device__ float g_k[N_KV * S_LEN * HEAD_DIM];

__device__ __nv_bfloat16 g_x_hi[S_LEN * HIDDEN];
__device__ __nv_bfloat16 g_x_lo[S_LEN * HIDDEN];
__device__ __nv_bfloat16 g_w_hi[QKV_N * HIDDEN];
__device__ __nv_bfloat16 g_w_lo[QKV_N * HIDDEN];
__device__ __nv_bfloat16 g_wo_hi[HIDDEN * HIDDEN];
__device__ __nv_bfloat16 g_wo_lo[HIDDEN * HIDDEN];
__device__ __nv_bfloat16 g_at_hi[S_LEN * HIDDEN];
__device__ __nv_bfloat16 g_at_lo[S_LEN * HIDDEN];

__device__ __nv_bfloat16 g_q_hi[N_HEADS * S_LEN * HEAD_DIM];
__device__ __nv_bfloat16 g_q_lo[N_HEADS * S_LEN * HEAD_DIM];
__device__ __nv_bfloat16 g_k_hi[N_KV * S_LEN * HEAD_DIM];
__device__ __nv_bfloat16 g_k_lo[N_KV * S_LEN * HEAD_DIM];
__device__ __nv_bfloat16 g_vT_hi[N_KV * HEAD_DIM * S_LEN];   // [kv][d][s]
__device__ __nv_bfloat16 g_vT_lo[N_KV * HEAD_DIM * S_LEN];

// ===================== low-level helpers =====================================
__device__ __forceinline__ uint32_t smem_u32(const void* p) {
    uint32_t a;
    asm("{ .reg .u64 t; cvta.to.shared.u64 t, %1; cvt.u32.u64 %0, t; }"
        : "=r"(a) : "l"(p));
    return a;
}
__device__ __forceinline__ void cp16(uint32_t s, const void* g) {
    asm volatile("cp.async.cg.shared.global [%0], [%1], 16;" :: "r"(s), "l"(g));
}
#define CP_COMMIT() asm volatile("cp.async.commit_group;" ::: "memory")
#define CP_WAIT2()  asm volatile("cp.async.wait_group 2;" ::: "memory")
#define CP_WAIT1()  asm volatile("cp.async.wait_group 1;" ::: "memory")
#define CP_WAIT0()  asm volatile("cp.async.wait_group 0;" ::: "memory")

__device__ __forceinline__ void ldm4(uint32_t& r0, uint32_t& r1, uint32_t& r2,
                                     uint32_t& r3, uint32_t a) {
    asm volatile("ldmatrix.sync.aligned.m8n8.x4.shared.b16 {%0,%1,%2,%3}, [%4];"
        : "=r"(r0), "=r"(r1), "=r"(r2), "=r"(r3) : "r"(a));
}
__device__ __forceinline__ void mma16816(float* c, const uint32_t* a,
                                         const uint32_t* b) {
    asm volatile(
        "mma.sync.aligned.m16n8k16.row.col.f32.bf16.bf16.f32 "
        "{%0,%1,%2,%3}, {%4,%5,%6,%7}, {%8,%9}, {%0,%1,%2,%3};"
        : "+f"(c[0]), "+f"(c[1]), "+f"(c[2]), "+f"(c[3])
        : "r"(a[0]), "r"(a[1]), "r"(a[2]), "r"(a[3]), "r"(b[0]), "r"(b[1]));
}

__device__ __forceinline__ uint32_t pack_hilo(float x, float y, uint32_t& lo) {
    __nv_bfloat16 hx = __float2bfloat16(x);
    __nv_bfloat16 hy = __float2bfloat16(y);
    __nv_bfloat16 lx = __float2bfloat16(x - __bfloat162float(hx));
    __nv_bfloat16 ly = __float2bfloat16(y - __bfloat162float(hy));
    lo = (uint32_t)__bfloat16_as_ushort(lx) | ((uint32_t)__bfloat16_as_ushort(ly) << 16);
    return (uint32_t)__bfloat16_as_ushort(hx) | ((uint32_t)__bfloat16_as_ushort(hy) << 16);
}

// ===================== mma.sync GEMM core (128x128, 2 CTA/SM) ================
#define ROW_STRIDE_B 80                 // 32 bf16 (64B) + 16B pad
#define MAT_BYTES (128 * ROW_STRIDE_B)  // 10240
#define STAGE_BYTES (4 * MAT_BYTES)     // 40960
#define GEMM_SMEM (2 * STAGE_BYTES)     // 81920  -> 2 CTAs/SM

__device__ __forceinline__ void load_stage(
    const __nv_bfloat16* a_hi, const __nv_bfloat16* a_lo,
    const __nv_bfloat16* b_hi, const __nv_bfloat16* b_lo,
    int K, int kb, uint32_t sbase, int tid)
{
    const __nv_bfloat16* ptrs[4] = {a_hi, a_lo, b_hi, b_lo};
    #pragma unroll
    for (int i = 0; i < 8; ++i) {
        int idx = tid + i * 256;        // 0..2047
        int mat = idx >> 9;             // 0..3
        int rem = idx & 511;
        int row = rem >> 2;
        int cp  = rem & 3;
        const __nv_bfloat16* src = ptrs[mat] + (size_t)row * K + kb + cp * 8;
        cp16(sbase + mat * MAT_BYTES + row * ROW_STRIDE_B + cp * 16, src);
    }
}

__device__ __forceinline__ void compute_stage(
    uint32_t sbase, int warp_m, int warp_n, int lane, float acc[2][8][4])
{
    const uint32_t ahB = sbase;
    const uint32_t alB = sbase + MAT_BYTES;
    const uint32_t bhB = sbase + 2 * MAT_BYTES;
    const uint32_t blB = sbase + 3 * MAT_BYTES;

    const int lrow = lane & 15;
    const int lk   = (lane >> 4) * 8;
    const int g    = lane >> 3;
    const int nadd = ((g >> 1) << 3) + (lane & 7);
    const int kadd = (g & 1) * 8;

    #pragma unroll
    for (int ks = 0; ks < 2; ++ks) {
        uint32_t ah[2][4], al[2][4];
        #pragma unroll
        for (int mf = 0; mf < 2; ++mf) {
            uint32_t off = (uint32_t)(warp_m * 32 + mf * 16 + lrow) * ROW_STRIDE_B
                         + (ks * 16 + lk) * 2;
            ldm4(ah[mf][0], ah[mf][1], ah[mf][2], ah[mf][3], ahB + off);
            ldm4(al[mf][0], al[mf][1], al[mf][2], al[mf][3], alB + off);
        }
        #pragma unroll
        for (int nf2 = 0; nf2 < 4; ++nf2) {
            uint32_t off = (uint32_t)(warp_n * 64 + nf2 * 16 + nadd) * ROW_STRIDE_B
                         + (ks * 16 + kadd) * 2;
            uint32_t bh[4], bl[4];
            ldm4(bh[0], bh[1], bh[2], bh[3], bhB + off);
            ldm4(bl[0], bl[1], bl[2], bl[3], blB + off);
            #pragma unroll
            for (int mf = 0; mf < 2; ++mf) {
                mma16816(acc[mf][nf2*2],   ah[mf], bh);
                mma16816(acc[mf][nf2*2],   ah[mf], bl);
                mma16816(acc[mf][nf2*2],   al[mf], bh);
                mma16816(acc[mf][nf2*2+1], ah[mf], bh + 2);
                mma16816(acc[mf][nf2*2+1], ah[mf], bl + 2);
                mma16816(acc[mf][nf2*2+1], al[mf], bh + 2);
            }
        }
    }
}

__device__ __forceinline__ void gemm_main(
    const __nv_bfloat16* ahi, const __nv_bfloat16* alo,
    const __nv_bfloat16* bhi, const __nv_bfloat16* blo,
    int K, char* sm, float acc[2][8][4])
{
    const int tid = threadIdx.x;
    const int wid = tid >> 5;
    const int lane = tid & 31;
    const int warp_m = wid & 3;
    const int warp_n = wid >> 2;
    const uint32_t smb = smem_u32(sm);

    #pragma unroll
    for (int mf = 0; mf < 2; ++mf)
        #pragma unroll
        for (int nf = 0; nf < 8; ++nf)
            #pragma unroll
            for (int r = 0; r < 4; ++r) acc[mf][nf][r] = 0.f;

    const int nIters = K / 32;      // 112
    load_stage(ahi, alo, bhi, blo, K, 0, smb, tid);
    CP_COMMIT();
    load_stage(ahi, alo, bhi, blo, K, 32, smb + STAGE_BYTES, tid);
    CP_COMMIT();

    for (int c = 0; c < nIters; ++c) {
        CP_WAIT1();
        __syncthreads();
        compute_stage(smb + (c & 1) * STAGE_BYTES, warp_m, warp_n, lane, acc);
        __syncthreads();
        if (c + 2 < nIters)
            load_stage(ahi, alo, bhi, blo, K, (c + 2) * 32,
                       smb + (c & 1) * STAGE_BYTES, tid);
        CP_COMMIT();
    }
    CP_WAIT0();
}

// ===================== QKV projection (V tiles scheduled first) ==============
__global__ __launch_bounds__(256, 2)
void qkv_mma_kernel(const float* __restrict__ bq, const float* __restrict__ bk,
                    const float* __restrict__ bv)
{
    extern __shared__ __align__(128) char sm[];
    const int m0 = blockIdx.x * 128;
    const int n0 = (35 - (int)blockIdx.y) * 128;   // reversed: V tiles first

    float acc[2][8][4];
    gemm_main(g_x_hi + (size_t)m0 * HIDDEN,
              g_x_lo + (size_t)m0 * HIDDEN,
              g_w_hi + (size_t)n0 * HIDDEN,
              g_w_lo + (size_t)n0 * HIDDEN,
              HIDDEN, sm, acc);

    const int tid = threadIdx.x;
    const int wid = tid >> 5;
    const int lane = tid & 31;
    const int warp_m = wid & 3;
    const int warp_n = wid >> 2;

    if (n0 < (N_HEADS + N_KV) * HEAD_DIM) {
        float* dst;
        const float* bias;
        if (n0 < N_HEADS * HEAD_DIM) {
            dst = g_q + (size_t)(n0 >> 7) * S_LEN * HEAD_DIM; bias = bq + n0;
        } else {
            int o = n0 - N_HEADS * HEAD_DIM;
            dst = g_k + (size_t)(o >> 7) * S_LEN * HEAD_DIM; bias = bk + o;
        }
        #pragma unroll
        for (int mf = 0; mf < 2; ++mf) {
            int row = m0 + warp_m * 32 + mf * 16 + (lane >> 2);
            #pragma unroll
            for (int nf = 0; nf < 8; ++nf) {
                int col = warp_n * 64 + nf * 8 + (lane & 3) * 2;
                float b0 = bias[col], b1 = bias[col + 1];
                dst[(size_t)row * HEAD_DIM + col]           = acc[mf][nf][0] + b0;
                dst[(size_t)row * HEAD_DIM + col + 1]       = acc[mf][nf][1] + b1;
                dst[(size_t)(row + 8) * HEAD_DIM + col]     = acc[mf][nf][2] + b0;
                dst[(size_t)(row + 8) * HEAD_DIM + col + 1] = acc[mf][nf][3] + b1;
            }
        }
    } else {
        int o = n0 - (N_HEADS + N_KV) * HEAD_DIM;
        int head = o >> 7;
        const float* bias = bv + o;

        __syncthreads();
        float* T = reinterpret_cast<float*>(sm);   // [128][133]
        #pragma unroll
        for (int mf = 0; mf < 2; ++mf) {
            int r0 = warp_m * 32 + mf * 16 + (lane >> 2);
            #pragma unroll
            for (int nf = 0; nf < 8; ++nf) {
                int col = warp_n * 64 + nf * 8 + (lane & 3) * 2;
                float b0 = bias[col], b1 = bias[col + 1];
                T[r0 * 133 + col]           = acc[mf][nf][0] + b0;
                T[r0 * 133 + col + 1]       = acc[mf][nf][1] + b1;
                T[(r0 + 8) * 133 + col]     = acc[mf][nf][2] + b0;
                T[(r0 + 8) * 133 + col + 1] = acc[mf][nf][3] + b1;
            }
        }
        __syncthreads();

        int d  = tid >> 1;
        int sc = (tid & 1) * 64;
        size_t base = (size_t)head * HEAD_DIM * S_LEN + (size_t)d * S_LEN + m0 + sc;
        __nv_bfloat16* hi = g_vT_hi + base;
        __nv_bfloat16* lo = g_vT_lo + base;
        #pragma unroll
        for (int j = 0; j < 64; j += 2) {
            float a = T[(sc + j) * 133 + d];
            float b = T[(sc + j + 1) * 133 + d];
            uint32_t L;
            uint32_t H = pack_hilo(a, b, L);
            *reinterpret_cast<uint32_t*>(hi + j) = H;
            *reinterpret_cast<uint32_t*>(lo + j) = L;
        }
    }
}

// ===================== output projection ====================================
__global__ __launch_bounds__(256, 2)
void out_mma_kernel(float* __restrict__ out)
{
    extern __shared__ __align__(128) char sm[];
    const int m0 = blockIdx.x * 128;
    const int n0 = blockIdx.y * 128;

    float acc[2][8][4];
    gemm_main(g_at_hi + (size_t)m0 * HIDDEN,
              g_at_lo + (size_t)m0 * HIDDEN,
              g_wo_hi + (size_t)n0 * HIDDEN,
              g_wo_lo + (size_t)n0 * HIDDEN,
              HIDDEN, sm, acc);

    const int tid = threadIdx.x;
    const int wid = tid >> 5;
    const int lane = tid & 31;
    const int warp_m = wid & 3;
    const int warp_n = wid >> 2;

    #pragma unroll
    for (int mf = 0; mf < 2; ++mf) {
        int row = m0 + warp_m * 32 + mf * 16 + (lane >> 2);
        #pragma unroll
        for (int nf = 0; nf < 8; ++nf) {
            int col = n0 + warp_n * 64 + nf * 8 + (lane & 3) * 2;
            out[(size_t)row * HIDDEN + col]           = acc[mf][nf][0];
            out[(size_t)row * HIDDEN + col + 1]       = acc[mf][nf][1];
            out[(size_t)(row + 8) * HIDDEN + col]     = acc[mf][nf][2];
            out[(size_t)(row + 8) * HIDDEN + col + 1] = acc[mf][nf][3];
        }
    }
}

// ===================== merged fp32 -> bf16 hi/lo split (MLP=2) ===============
#define CVT_X  (S_LEN * HIDDEN / 4)
#define CVT_WQ (N_HEADS * HEAD_DIM * HIDDEN / 4)
#define CVT_WK (N_KV * HEAD_DIM * HIDDEN / 4)
#define CVT_WO (HIDDEN * HIDDEN / 4)
#define CVT_TOTAL (CVT_X + CVT_WQ + 2 * CVT_WK + CVT_WO)
#define CVT_HALF (CVT_TOTAL / 2)          // 4587520 (CVT_TOTAL is even)

__device__ __forceinline__ void cvt_one(
    const float* __restrict__ X, const float* __restrict__ Wq,
    const float* __restrict__ Wk, const float* __restrict__ Wv,
    const float* __restrict__ Wo, int i)
{
    const float* src;
    __nv_bfloat16 *hi, *lo;
    int j;
    if (i < CVT_X) {
        src = X; j = i; hi = g_x_hi; lo = g_x_lo;
    } else if (i < CVT_X + CVT_WQ) {
        src = Wq; j = i - CVT_X; hi = g_w_hi; lo = g_w_lo;
    } else if (i < CVT_X + CVT_WQ + CVT_WK) {
        src = Wk; j = i - CVT_X - CVT_WQ;
        hi = g_w_hi + (size_t)N_HEADS * HEAD_DIM * HIDDEN;
        lo = g_w_lo + (size_t)N_HEADS * HEAD_DIM * HIDDEN;
    } else if (i < CVT_X + CVT_WQ + 2 * CVT_WK) {
        src = Wv; j = i - CVT_X - CVT_WQ - CVT_WK;
        hi = g_w_hi + (size_t)(N_HEADS + N_KV) * HEAD_DIM * HIDDEN;
        lo = g_w_lo + (size_t)(N_HEADS + N_KV) * HEAD_DIM * HIDDEN;
    } else {
        src = Wo; j = i - CVT_X - CVT_WQ - 2 * CVT_WK;
        hi = g_wo_hi; lo = g_wo_lo;
    }

    float4 v = reinterpret_cast<const float4*>(src)[j];
    __nv_bfloat16 h0 = __float2bfloat16(v.x);
    __nv_bfloat16 h1 = __float2bfloat16(v.y);
    __nv_bfloat16 h2 = __float2bfloat16(v.z);
    __nv_bfloat16 h3 = __float2bfloat16(v.w);
    __nv_bfloat16 l0 = __float2bfloat16(v.x - __bfloat162float(h0));
    __nv_bfloat16 l1 = __float2bfloat16(v.y - __bfloat162float(h1));
    __nv_bfloat16 l2 = __float2bfloat16(v.z - __bfloat162float(h2));
    __nv_bfloat16 l3 = __float2bfloat16(v.w - __bfloat162float(h3));
    ushort4 hv, lv;
    hv.x = __bfloat16_as_ushort(h0); hv.y = __bfloat16_as_ushort(h1);
    hv.z = __bfloat16_as_ushort(h2); hv.w = __bfloat16_as_ushort(h3);
    lv.x = __bfloat16_as_ushort(l0); lv.y = __bfloat16_as_ushort(l1);
    lv.z = __bfloat16_as_ushort(l2); lv.w = __bfloat16_as_ushort(l3);
    reinterpret_cast<ushort4*>(hi)[j] = hv;
    reinterpret_cast<ushort4*>(lo)[j] = lv;
}

__global__ void cvt_all_kernel(const float* __restrict__ X,
                               const float* __restrict__ Wq,
                               const float* __restrict__ Wk,
                               const float* __restrict__ Wv,
                               const float* __restrict__ Wo)
{
    int i = blockIdx.x * blockDim.x + threadIdx.x;
    if (i >= CVT_HALF) return;
    cvt_one(X, Wq, Wk, Wv, Wo, i);               // two independent elements:
    cvt_one(X, Wq, Wk, Wv, Wo, i + CVT_HALF);    // loads overlap (MLP=2)
}

// ===================== RoPE + convert (vectorized x4) ========================
__global__ void rope_cvt_kernel(const float* __restrict__ cos_t,
                                const float* __restrict__ sin_t)
{
    int idx = blockIdx.x * blockDim.x + threadIdx.x;   // (N_HEADS+N_KV)*S*16
    if (idx >= (N_HEADS + N_KV) * S_LEN * 16) return;
    int d0 = (idx & 15) * 4;
    int s  = (idx >> 4) & (S_LEN - 1);
    int head = idx >> 15;

    const float* p;
    __nv_bfloat16 *hi, *lo;
    size_t base;
    if (head < N_HEADS) {
        base = (size_t)head * S_LEN * HEAD_DIM;
        p = g_q + base; hi = g_q_hi + base; lo = g_q_lo + base;
    } else {
        base = (size_t)(head - N_HEADS) * S_LEN * HEAD_DIM;
        p = g_k + base; hi = g_k_hi + base; lo = g_k_lo + base;
    }
    size_t o1 = (size_t)s * HEAD_DIM + d0;
    size_t o2 = o1 + 64;
    float4 c  = *reinterpret_cast<const float4*>(cos_t + s * HEAD_DIM + d0);
    float4 sn = *reinterpret_cast<const float4*>(sin_t + s * HEAD_DIM + d0);
    float4 x1 = *reinterpret_cast<const float4*>(p + o1);
    float4 x2 = *reinterpret_cast<const float4*>(p + o2);

    float y1[4], y2[4];
    y1[0] = x1.x * c.x - x2.x * sn.x;  y2[0] = x2.x * c.x + x1.x * sn.x;
    y1[1] = x1.y * c.y - x2.y * sn.y;  y2[1] = x2.y * c.y + x1.y * sn.y;
    y1[2] = x1.z * c.z - x2.z * sn.z;  y2[2] = x2.z * c.z + x1.z * sn.z;
    y1[3] = x1.w * c.w - x2.w * sn.w;  y2[3] = x2.w * c.w + x1.w * sn.w;

    uint2 H, L;
    uint32_t l0, l1;
    H.x = pack_hilo(y1[0], y1[1], l0);
    H.y = pack_hilo(y1[2], y1[3], l1);
    L.x = l0; L.y = l1;
    *reinterpret_cast<uint2*>(hi + o1) = H;
    *reinterpret_cast<uint2*>(lo + o1) = L;
    H.x = pack_hilo(y2[0], y2[1], l0);
    H.y = pack_hilo(y2[2], y2[3], l1);
    L.x = l0; L.y = l1;
    *reinterpret_cast<uint2*>(hi + o2) = H;
    *reinterpret_cast<uint2*>(lo + o2) = L;
}

// ===================== flash attention (software-pipelined S) =================
#define FL_QH 0u
#define FL_QL 34816u
#define FL_ST0 69632u
#define FL_STAGE 71680u
#define FL_KH 0u
#define FL_KL 17408u
#define FL_VH 34816u
#define FL_VL 53248u
#define FLASH_SMEM 212992

__device__ __forceinline__ void flash_load_k(
    uint32_t sbase, const __nv_bfloat16* kh_g, const __nv_bfloat16* kl_g,
    int key0, int tid)
{
    #pragma unroll
    for (int i = 0; i < 4; ++i) {
        int idx = tid + i * 256;
        int row = idx >> 4, cp = idx & 15;
        cp16(sbase + FL_KH + row * 272 + cp * 16,
             kh_g + (size_t)(key0 + row) * HEAD_DIM + cp * 8);
        cp16(sbase + FL_KL + row * 272 + cp * 16,
             kl_g + (size_t)(key0 + row) * HEAD_DIM + cp * 8);
    }
}
__device__ __forceinline__ void flash_load_v(
    uint32_t sbase, const __nv_bfloat16* vh_g, const __nv_bfloat16* vl_g,
    int key0, int tid)
{
    #pragma unroll
    for (int i = 0; i < 4; ++i) {
        int idx = tid + i * 256;
        int vrow = idx >> 3, vcp = idx & 7;
        cp16(sbase + FL_VH + vrow * 144 + vcp * 16,
             vh_g + (size_t)vrow * S_LEN + key0 + vcp * 8);
        cp16(sbase + FL_VL + vrow * 144 + vcp * 16,
             vl_g + (size_t)vrow * S_LEN + key0 + vcp * 8);
    }
}

__device__ __forceinline__ void flash_qk(
    float s[8][4], uint32_t smb, uint32_t stg,
    int wid, int lrow, int lk, int nadd, int kadd)
{
    #pragma unroll
    for (int nf = 0; nf < 8; ++nf)
        #pragma unroll
        for (int r = 0; r < 4; ++r) s[nf][r] = 0.f;
    #pragma unroll
    for (int ks = 0; ks < 8; ++ks) {
        uint32_t qh[4], ql[4];
        uint32_t qoff = (uint32_t)(wid * 16 + lrow) * 272 + (ks * 16 + lk) * 2;
        ldm4(qh[0], qh[1], qh[2], qh[3], smb + FL_QH + qoff);
        ldm4(ql[0], ql[1], ql[2], ql[3], smb + FL_QL + qoff);
        #pragma unroll
        for (int nf2 = 0; nf2 < 4; ++nf2) {
            uint32_t koff = (uint32_t)(nf2 * 16 + nadd) * 272 + (ks * 16 + kadd) * 2;
            uint32_t kh[4], kl[4];
            ldm4(kh[0], kh[1], kh[2], kh[3], stg + FL_KH + koff);
            ldm4(kl[0], kl[1], kl[2], kl[3], stg + FL_KL + koff);
            mma16816(s[nf2*2],   qh, kh);
            mma16816(s[nf2*2],   qh, kl);
            mma16816(s[nf2*2],   ql, kh);
            mma16816(s[nf2*2+1], qh, kh + 2);
            mma16816(s[nf2*2+1], qh, kl + 2);
            mma16816(s[nf2*2+1], ql, kh + 2);
        }
    }
}

__global__ __launch_bounds__(256, 1)
void flash_mma_kernel()
{
    extern __shared__ __align__(128) char sm[];
    const uint32_t smb = smem_u32(sm);
    const int qb  = 15 - (int)blockIdx.x;
    const int h   = blockIdx.y;
    const int kvh = h / GROUPS;
    const int tid = threadIdx.x;
    const int wid = tid >> 5;
    const int lane = tid & 31;
    const int lrow = lane & 15;
    const int lk   = (lane >> 4) * 8;
    const int g    = lane >> 3;
    const int nadd = ((g >> 1) << 3) + (lane & 7);
    const int kadd = (g & 1) * 8;

    const __nv_bfloat16* qh_g = g_q_hi + ((size_t)h * S_LEN + qb * 128) * HEAD_DIM;
    const __nv_bfloat16* ql_g = g_q_lo + ((size_t)h * S_LEN + qb * 128) * HEAD_DIM;
    const __nv_bfloat16* kh_g = g_k_hi + (size_t)kvh * S_LEN * HEAD_DIM;
    const __nv_bfloat16* kl_g = g_k_lo + (size_t)kvh * S_LEN * HEAD_DIM;
    const __nv_bfloat16* vh_g = g_vT_hi + (size_t)kvh * HEAD_DIM * S_LEN;
    const __nv_bfloat16* vl_g = g_vT_lo + (size_t)kvh * HEAD_DIM * S_LEN;

    const int nblk = 2 * qb + 2;

    #pragma unroll
    for (int i = 0; i < 8; ++i) {
        int idx = tid + i * 256;
        int row = idx >> 4, cp = idx & 15;
        cp16(smb + FL_QH + row * 272 + cp * 16, qh_g + (size_t)row * HEAD_DIM + cp * 8);
        cp16(smb + FL_QL + row * 272 + cp * 16, ql_g + (size_t)row * HEAD_DIM + cp * 8);
    }
    flash_load_k(smb + FL_ST0, kh_g, kl_g, 0, tid);
    flash_load_v(smb + FL_ST0, vh_g, vl_g, 0, tid);
    CP_COMMIT();
    flash_load_k(smb + FL_ST0 + FL_STAGE, kh_g, kl_g, 64, tid);
    CP_COMMIT();
    flash_load_v(smb + FL_ST0 + FL_STAGE, vh_g, vl_g, 64, tid);
    CP_COMMIT();

    CP_WAIT2();
    __syncthreads();
    float s_cur[8][4];
    flash_qk(s_cur, smb, smb + FL_ST0, wid, lrow, lk, nadd, kadd);

    float o[16][4];
    #pragma unroll
    for (int nf = 0; nf < 16; ++nf)
        #pragma unroll
        for (int r = 0; r < 4; ++r) o[nf][r] = 0.f;
    float m0 = -1e30f, m1 = -1e30f, l0 = 0.f, l1 = 0.f;
    const int qr0 = qb * 128 + wid * 16 + (lane >> 2);
    const int qr1 = qr0 + 8;

    for (int blk = 0; blk < nblk; ++blk) {
        const int key0 = blk * 64;
        const uint32_t stg_cur  = smb + FL_ST0 + (blk & 1) * FL_STAGE;
        const uint32_t stg_next = smb + FL_ST0 + ((blk + 1) & 1) * FL_STAGE;

        CP_WAIT1();
        __syncthreads();

        float s_next[8][4];
        if (blk + 1 < nblk)
            flash_qk(s_next, smb, stg_next, wid, lrow, lk, nadd, kadd);

        if (blk + 2 < nblk)
            flash_load_k(stg_cur, kh_g, kl_g, (blk + 2) * 64, tid);
        CP_COMMIT();

        if (blk >= 2 * qb) {
            #pragma unroll
            for (int nf = 0; nf < 8; ++nf) {
                int c0 = key0 + 8 * nf + 2 * (lane & 3);
                s_cur[nf][0] = (c0     > qr0) ? -1e30f : s_cur[nf][0] * ATTN_SCALE;
                s_cur[nf][1] = (c0 + 1 > qr0) ? -1e30f : s_cur[nf][1] * ATTN_SCALE;
                s_cur[nf][2] = (c0     > qr1) ? -1e30f : s_cur[nf][2] * ATTN_SCALE;
                s_cur[nf][3] = (c0 + 1 > qr1) ? -1e30f : s_cur[nf][3] * ATTN_SCALE;
            }
        } else {
            #pragma unroll
            for (int nf = 0; nf < 8; ++nf)
                #pragma unroll
                for (int r = 0; r < 4; ++r) s_cur[nf][r] *= ATTN_SCALE;
        }

        float mx0 = -1e30f, mx1 = -1e30f;
        #pragma unroll
        for (int nf = 0; nf < 8; ++nf) {
            mx0 = fmaxf(mx0, fmaxf(s_cur[nf][0], s_cur[nf][1]));
            mx1 = fmaxf(mx1, fmaxf(s_cur[nf][2], s_cur[nf][3]));
        }
        mx0 = fmaxf(mx0, __shfl_xor_sync(0xffffffffu, mx0, 1));
        mx0 = fmaxf(mx0, __shfl_xor_sync(0xffffffffu, mx0, 2));
        mx1 = fmaxf(mx1, __shfl_xor_sync(0xffffffffu, mx1, 1));
        mx1 = fmaxf(mx1, __shfl_xor_sync(0xffffffffu, mx1, 2));

        float mn0 = fmaxf(m0, mx0), mn1 = fmaxf(m1, mx1);
        float corr0 = __expf(m0 - mn0), corr1 = __expf(m1 - mn1);
        float sum0 = 0.f, sum1 = 0.f;
        #pragma unroll
        for (int nf = 0; nf < 8; ++nf) {
            s_cur[nf][0] = __expf(s_cur[nf][0] - mn0);
            s_cur[nf][1] = __expf(s_cur[nf][1] - mn0);
            s_cur[nf][2] = __expf(s_cur[nf][2] - mn1);
            s_cur[nf][3] = __expf(s_cur[nf][3] - mn1);
            sum0 += s_cur[nf][0] + s_cur[nf][1];
            sum1 += s_cur[nf][2] + s_cur[nf][3];
        }
        sum0 += __shfl_xor_sync(0xffffffffu, sum0, 1);
        sum0 += __shfl_xor_sync(0xffffffffu, sum0, 2);
        sum1 += __shfl_xor_sync(0xffffffffu, sum1, 1);
        sum1 += __shfl_xor_sync(0xffffffffu, sum1, 2);
        l0 = l0 * corr0 + sum0;  m0 = mn0;
        l1 = l1 * corr1 + sum1;  m1 = mn1;

        #pragma unroll
        for (int nf = 0; nf < 16; ++nf) {
            o[nf][0] *= corr0; o[nf][1] *= corr0;
            o[nf][2] *= corr1; o[nf][3] *= corr1;
        }

        #pragma unroll
        for (int ks = 0; ks < 4; ++ks) {
            int f0 = 2 * ks, f1 = f0 + 1;
            uint32_t ph[4], pl[4];
            ph[0] = pack_hilo(s_cur[f0][0], s_cur[f0][1], pl[0]);
            ph[1] = pack_hilo(s_cur[f0][2], s_cur[f0][3], pl[1]);
            ph[2] = pack_hilo(s_cur[f1][0], s_cur[f1][1], pl[2]);
            ph[3] = pack_hilo(s_cur[f1][2], s_cur[f1][3], pl[3]);
            #pragma unroll
            for (int nf2 = 0; nf2 < 8; ++nf2) {
                uint32_t voff = (uint32_t)(nf2 * 16 + nadd) * 144 + (ks * 16 + kadd) * 2;
                uint32_t vh[4], vl[4];
                ldm4(vh[0], vh[1], vh[2], vh[3], stg_cur + FL_VH + voff);
                ldm4(vl[0], vl[1], vl[2], vl[3], stg_cur + FL_VL + voff);
                mma16816(o[nf2*2],   ph, vh);
                mma16816(o[nf2*2],   pl, vh);
                mma16816(o[nf2*2],   ph, vl);
                mma16816(o[nf2*2+1], ph, vh + 2);
                mma16816(o[nf2*2+1], pl, vh + 2);
                mma16816(o[nf2*2+1], ph, vl + 2);
            }
        }

        __syncthreads();
        if (blk + 2 < nblk)
            flash_load_v(stg_cur, vh_g, vl_g, (blk + 2) * 64, tid);
        CP_COMMIT();

        #pragma unroll
        for (int nf = 0; nf < 8; ++nf)
            #pragma unroll
            for (int r = 0; r < 4; ++r) s_cur[nf][r] = s_next[nf][r];
    }

    float inv0 = 1.f / l0, inv1 = 1.f / l1;
    #pragma unroll
    for (int nf = 0; nf < 16; ++nf) {
        int dcol = 8 * nf + 2 * (lane & 3);
        size_t o0 = (size_t)qr0 * HIDDEN + h * HEAD_DIM + dcol;
        size_t o1 = (size_t)qr1 * HIDDEN + h * HEAD_DIM + dcol;
        uint32_t lo;
        uint32_t hi = pack_hilo(o[nf][0] * inv0, o[nf][1] * inv0, lo);
        *reinterpret_cast<uint32_t*>(g_at_hi + o0) = hi;
        *reinterpret_cast<uint32_t*>(g_at_lo + o0) = lo;
        hi = pack_hilo(o[nf][2] * inv1, o[nf][3] * inv1, lo);
        *reinterpret_cast<uint32_t*>(g_at_hi + o1) = hi;
        *reinterpret_cast<uint32_t*>(g_at_lo + o1) = lo;
    }
}

// ===================== launch ================================================
extern "C" void kernel_launch(void* const* d_in, const int* in_sizes, int n_in,
                              void* d_out, int out_size)
{
    const float* X    = (const float*)d_in[0];
    const float* cosT = (const float*)d_in[1];
    const float* sinT = (const float*)d_in[2];
    const float* Wq   = (const float*)d_in[3];
    const float* bq   = (const float*)d_in[4];
    const float* Wk   = (const float*)d_in[5];
    const float* bk   = (const float*)d_in[6];
    const float* Wv   = (const float*)d_in[7];
    const float* bv   = (const float*)d_in[8];
    const float* Wo   = (const float*)d_in[9];
    float* out = (float*)d_out;

    cudaFuncSetAttribute(qkv_mma_kernel,  cudaFuncAttributeMaxDynamicSharedMemorySize, GEMM_SMEM);
    cudaFuncSetAttribute(out_mma_kernel,  cudaFuncAttributeMaxDynamicSharedMemorySize, GEMM_SMEM);
    cudaFuncSetAttribute(flash_mma_kernel, cudaFuncAttributeMaxDynamicSharedMemorySize, FLASH_SMEM);

    // 1) merged conversion kernel (2 independent elements/thread, MLP=2)
    cvt_all_kernel<<<(CVT_HALF + 255) / 256, 256>>>(X, Wq, Wk, Wv, Wo);

    // 2) QKV projection (V tiles first)
    qkv_mma_kernel<<<dim3(16, 36), 256, GEMM_SMEM>>>(bq, bk, bv);

    // 3) RoPE -> bf16 hi/lo (vectorized)
    {
        int n = (N_HEADS + N_KV) * S_LEN * 16;
        rope_cvt_kernel<<<(n + 255) / 256, 256>>>(cosT, sinT);
    }

    // 4) flash attention (software-pipelined)
    flash_mma_kernel<<<dim3(16, N_HEADS), 256, FLASH_SMEM>>>();

    // 5) output projection (full-K, direct stores)
    out_mma_kernel<<<dim3(16, 28), 256, GEMM_SMEM>>>(out);
}